// round 14
// baseline (speedup 1.0000x reference)
#include <cuda_runtime.h>
#include <cstdint>

#define SDIM 1024
#define BHN  64
#define THREADS 256
#define KT    64
#define SLOT_BYTES 65536              /* A: 32KB (128x64 f32) + B: 32KB (64x128) */
#define STAGES 3
#define SMEM_BYTES (STAGES * SLOT_BYTES)   /* 192KB, 1 CTA/SM */
#define NITER (SDIM / KT)             /* 16 */

// 256 MB scratch for attention probabilities.
__device__ __align__(16) float g_attn[(size_t)BHN * SDIM * SDIM];

__device__ __forceinline__ uint32_t f2tf(float x) {
    uint32_t r;
    asm("cvt.rna.tf32.f32 %0, %1;" : "=r"(r) : "f"(x));
    return r;
}

__device__ __forceinline__ uint32_t smem_u32(const void* p) {
    uint32_t a;
    asm("{ .reg .u64 t; cvta.to.shared.u64 t, %1; cvt.u32.u64 %0, t; }"
        : "=r"(a) : "l"(p));
    return a;
}

__device__ __forceinline__ void cp16(uint32_t smem_dst, const void* gmem_src) {
    asm volatile("cp.async.cg.shared.global [%0], [%1], 16;"
                 :: "r"(smem_dst), "l"(gmem_src) : "memory");
}

__device__ __forceinline__ void cp_commit() {
    asm volatile("cp.async.commit_group;" ::: "memory");
}

__device__ __forceinline__ void cp_wait1() {
    asm volatile("cp.async.wait_group 1;" ::: "memory");
}

__device__ __forceinline__ void ldsm4(uint32_t a[4], uint32_t addr) {
    asm volatile("ldmatrix.sync.aligned.m8n8.x4.shared.b16 {%0,%1,%2,%3}, [%4];"
        : "=r"(a[0]), "=r"(a[1]), "=r"(a[2]), "=r"(a[3]) : "r"(addr));
}

__device__ __forceinline__ uint32_t lds32(uint32_t addr) {
    uint32_t v;
    asm volatile("ld.shared.b32 %0, [%1];" : "=r"(v) : "r"(addr));
    return v;
}

__device__ __forceinline__ void mma_tf32(float c[4], const uint32_t a[4],
                                         uint32_t b0, uint32_t b1) {
    asm volatile(
        "mma.sync.aligned.m16n8k8.row.col.f32.tf32.tf32.f32 "
        "{%0,%1,%2,%3}, {%4,%5,%6,%7}, {%8,%9}, {%0,%1,%2,%3};"
        : "+f"(c[0]), "+f"(c[1]), "+f"(c[2]), "+f"(c[3])
        : "r"(a[0]), "r"(a[1]), "r"(a[2]), "r"(a[3]), "r"(b0), "r"(b1));
}

// CTA tile 128x128, KT=64, 8 warps (2x4), warp tile 64x32, mma m16n8k8 tf32.
// 3-stage cp.async ring (64KB slots, 192KB total -> 1 CTA/SM, no reg cap),
// ONE __syncthreads per iteration, fill issued before compute.
// A smem: [m][64w] 256B rows, 16B-chunk swizzle ch^(m&7)  -> ldmatrix.x4 reads.
// B smem: [k][128w] 512B rows, word swizzle n^((k&7)<<3)  -> conflict-free LDS.32.
// CVT_A/CVT_B: tf32-round fragments in-loop (for raw-fp32 operands).
// FUSE: out = (acc + AddM)*scale + Mask  (QK -> g_attn); else out = acc.
template<int CVT_A, int CVT_B, int FUSE>
__global__ __launch_bounds__(THREADS, 1) void gemm_kernel(
    const float* __restrict__ Ag, const float* __restrict__ Bg,
    const float* __restrict__ AddM, const float* __restrict__ Mask,
    float* __restrict__ Out)
{
    extern __shared__ __align__(128) char smem[];
    const uint32_t sbase = smem_u32(smem);

    const int bm = blockIdx.x, bn = blockIdx.y, bh = blockIdx.z;
    const int tid  = threadIdx.x;
    const int warp = tid >> 5, lane = tid & 31;
    const int wm = warp >> 2, wn = warp & 3;   // 2 x 4 warp grid
    const int lr = lane >> 2, lc = lane & 3;

    const size_t mat = (size_t)bh * SDIM * SDIM;
    const float* Abase = Ag + mat + (size_t)(bm * 128) * SDIM;
    const float* Bbase = Bg + mat + bn * 128;

    float c[4][4][4];
    #pragma unroll
    for (int i = 0; i < 4; i++)
        #pragma unroll
        for (int j = 0; j < 4; j++)
            #pragma unroll
            for (int r = 0; r < 4; r++) c[i][j][r] = 0.f;

    // A fragment geometry (ldmatrix), verified rounds 3/5-12 (rows now 256B).
    const int moff = ((lane >> 3) & 1) * 8 + (lane & 7);
    const int csel = lane >> 4;
    uint32_t a_base[4];
    int      a_m7[4];
    #pragma unroll
    for (int ti = 0; ti < 4; ti++) {
        int m = wm * 64 + ti * 16 + moff;
        a_base[ti] = (uint32_t)m * 256u;
        a_m7[ti]   = m & 7;
    }
    // B fragment geometry: lane holds n = wn*32 + tj*8 + lr, k = kk + lc (+4).
    uint32_t nxb[4];
    #pragma unroll
    for (int tj = 0; tj < 4; tj++) {
        int n = wn * 32 + tj * 8 + lr;
        nxb[tj] = (uint32_t)((n ^ (lc << 3)) << 2);
    }

    // Per-thread fill coordinates (256 threads: 8 x 16B each for A and B).
    const int fa_r  = tid >> 4;          // A rows fa_r + 16*i   (16 chunks/row)
    const int fa_ch = tid & 15;
    const int fb_k  = tid >> 5;          // B k-rows fb_k + 8*i  (32 chunks/row)
    const int fb_nq = (tid & 31) << 2;
    uint32_t a_dst[8], b_dst[8];
    const float* a_src[8];
    const float* b_src[8];
    #pragma unroll
    for (int i = 0; i < 8; i++) {
        int r = fa_r + i * 16;
        a_dst[i] = (uint32_t)(r * 256 + ((fa_ch ^ (r & 7)) << 4));
        a_src[i] = Abase + (size_t)r * SDIM + fa_ch * 4;
        int k = fb_k + i * 8;
        b_dst[i] = (uint32_t)(32768 + k * 512 + ((fb_nq ^ ((k & 7) << 3)) << 2));
        b_src[i] = Bbase + (size_t)k * SDIM + fb_nq;
    }

    auto fill = [&](int stage, int kt) {
        const uint32_t s0 = sbase + stage * SLOT_BYTES;
        #pragma unroll
        for (int i = 0; i < 8; ++i) cp16(s0 + a_dst[i], a_src[i] + kt);
        #pragma unroll
        for (int i = 0; i < 8; ++i) cp16(s0 + b_dst[i], b_src[i] + (size_t)kt * SDIM);
    };

    auto compute = [&](int stage) {
        const uint32_t sA = sbase + stage * SLOT_BYTES;
        const uint32_t sB = sA + 32768;
        #pragma unroll
        for (int kk4 = 0; kk4 < 8; ++kk4) {
            uint32_t af[4][4];
            const int chunk = (kk4 << 1) + csel;
            #pragma unroll
            for (int ti = 0; ti < 4; ++ti)
                ldsm4(af[ti], sA + a_base[ti] + (uint32_t)((chunk ^ a_m7[ti]) << 4));

            uint32_t b0[4], b1[4];
            const uint32_t row0 = sB + (uint32_t)((kk4 << 3) + lc) * 512u;
            const uint32_t row1 = row0 + 2048u;
            #pragma unroll
            for (int tj = 0; tj < 4; ++tj) {
                b0[tj] = lds32(row0 + nxb[tj]);
                b1[tj] = lds32(row1 + (nxb[tj] ^ 128u));
            }
            if (CVT_A) {
                #pragma unroll
                for (int ti = 0; ti < 4; ++ti)
                    #pragma unroll
                    for (int j = 0; j < 4; ++j)
                        af[ti][j] = f2tf(__uint_as_float(af[ti][j]));
            }
            if (CVT_B) {
                #pragma unroll
                for (int tj = 0; tj < 4; ++tj) {
                    b0[tj] = f2tf(__uint_as_float(b0[tj]));
                    b1[tj] = f2tf(__uint_as_float(b1[tj]));
                }
            }
            #pragma unroll
            for (int ti = 0; ti < 4; ++ti)
                #pragma unroll
                for (int tj = 0; tj < 4; ++tj)
                    mma_tf32(c[ti][tj], af[ti], b0[tj], b1[tj]);
        }
    };

    // One pipeline step with compile-time stage: wait tile `it`, publish,
    // issue fill for tile it+2 (slot last read at it-1 -> WAR fenced by the
    // barrier), then compute tile `it`.
    auto step = [&](int it, int stage) {
        cp_wait1();
        __syncthreads();
        if (it + 2 < NITER) { fill((it + 2) % STAGES, (it + 2) * KT); }
        cp_commit();
        compute(stage);
    };

    // Prologue: STAGES-1 tiles in flight.
    fill(0, 0);   cp_commit();
    fill(1, KT);  cp_commit();

    #pragma unroll 1
    for (int it = 0; it < 15; it += 3) {
        step(it + 0, 0);
        step(it + 1, 1);
        step(it + 2, 2);
    }
    step(15, 0);

    // ---- epilogue ----
    const float scale = 0.03125f;  // 1/sqrt(1024)
    #pragma unroll
    for (int ti = 0; ti < 4; ti++) {
        #pragma unroll
        for (int tj = 0; tj < 4; tj++) {
            int i0 = bm * 128 + wm * 64 + ti * 16 + lr;
            int j0 = bn * 128 + wn * 32 + tj * 8 + lc * 2;
            #pragma unroll
            for (int h = 0; h < 2; h++) {
                int i = i0 + h * 8;
                float v0 = c[ti][tj][h * 2 + 0];
                float v1 = c[ti][tj][h * 2 + 1];
                size_t off = mat + (size_t)i * SDIM + j0;
                if (FUSE) {
                    float2 bb = *reinterpret_cast<const float2*>(AddM + off);
                    float2 mm = *reinterpret_cast<const float2*>(
                        Mask + (size_t)i * SDIM + j0);
                    v0 = (v0 + bb.x) * scale + mm.x;
                    v1 = (v1 + bb.y) * scale + mm.y;
                }
                float2 o; o.x = v0; o.y = v1;
                *reinterpret_cast<float2*>(Out + off) = o;
            }
        }
    }
}

// One CTA (256 threads) per row; in-place softmax, tf32-rounded output.
__global__ __launch_bounds__(256) void softmax_kernel() {
    const size_t row = blockIdx.x;
    float* p = g_attn + row * SDIM;
    const int tid = threadIdx.x;
    const int warp = tid >> 5, lane = tid & 31;
    __shared__ float sred[8];

    float4 v = reinterpret_cast<float4*>(p)[tid];

    float m = fmaxf(fmaxf(v.x, v.y), fmaxf(v.z, v.w));
    #pragma unroll
    for (int o = 16; o; o >>= 1) m = fmaxf(m, __shfl_xor_sync(0xffffffffu, m, o));
    if (lane == 0) sred[warp] = m;
    __syncthreads();
    m = sred[0];
    #pragma unroll
    for (int i = 1; i < 8; i++) m = fmaxf(m, sred[i]);
    __syncthreads();

    v.x = __expf(v.x - m);
    v.y = __expf(v.y - m);
    v.z = __expf(v.z - m);
    v.w = __expf(v.w - m);
    float s = v.x + v.y + v.z + v.w;
    #pragma unroll
    for (int o = 16; o; o >>= 1) s += __shfl_xor_sync(0xffffffffu, s, o);
    if (lane == 0) sred[warp] = s;
    __syncthreads();
    s = sred[0];
    #pragma unroll
    for (int i = 1; i < 8; i++) s += sred[i];

    float inv = 1.0f / s;
    v.x = __uint_as_float(f2tf(v.x * inv));
    v.y = __uint_as_float(f2tf(v.y * inv));
    v.z = __uint_as_float(f2tf(v.z * inv));
    v.w = __uint_as_float(f2tf(v.w * inv));
    reinterpret_cast<float4*>(p)[tid] = v;
}

extern "C" void kernel_launch(void* const* d_in, const int* in_sizes, int n_in,
                              void* d_out, int out_size) {
    const float* A    = (const float*)d_in[0];
    const float* J    = (const float*)d_in[1];
    const float* B    = (const float*)d_in[2];
    const float* P    = (const float*)d_in[3];
    const float* mask = (const float*)d_in[4];
    float* out = (float*)d_out;

    float* attn = nullptr;
    cudaGetSymbolAddress((void**)&attn, g_attn);

    cudaFuncSetAttribute(gemm_kernel<1, 1, 1>,
                         cudaFuncAttributeMaxDynamicSharedMemorySize, SMEM_BYTES);
    cudaFuncSetAttribute(gemm_kernel<0, 1, 0>,
                         cudaFuncAttributeMaxDynamicSharedMemorySize, SMEM_BYTES);

    dim3 grid(SDIM / 128, SDIM / 128, BHN);  // 8 x 8 x 64

    // gemm1: raw A x raw J (cvt both in-loop), fused (+B)*scale+mask epilogue.
    gemm_kernel<1, 1, 1><<<grid, THREADS, SMEM_BYTES>>>(A, J, B, mask, attn);
    // softmax emits tf32-rounded probs -> gemm2 converts only P in-loop.
    softmax_kernel<<<BHN * SDIM, 256>>>();
    gemm_kernel<0, 1, 0><<<grid, THREADS, SMEM_BYTES>>>(attn, P, nullptr, nullptr, out);
}

// round 15
// speedup vs baseline: 1.1869x; 1.1869x over previous
#include <cuda_runtime.h>
#include <cstdint>

#define SDIM 1024
#define BHN  64
#define THREADS 128
#define SLOT_BYTES 32768              /* A: 16KB (128x32 f32) + B: 16KB (32x128) */
#define STAGES 3
#define SMEM_BYTES (STAGES * SLOT_BYTES)   /* 96KB, 2 CTA/SM */

// 256 MB scratch for attention probabilities.
__device__ __align__(16) float g_attn[(size_t)BHN * SDIM * SDIM];

__device__ __forceinline__ uint32_t f2tf(float x) {
    uint32_t r;
    asm("cvt.rna.tf32.f32 %0, %1;" : "=r"(r) : "f"(x));
    return r;
}

__device__ __forceinline__ uint32_t smem_u32(const void* p) {
    uint32_t a;
    asm("{ .reg .u64 t; cvta.to.shared.u64 t, %1; cvt.u32.u64 %0, t; }"
        : "=r"(a) : "l"(p));
    return a;
}

__device__ __forceinline__ void cp16(uint32_t smem_dst, const void* gmem_src) {
    asm volatile("cp.async.cg.shared.global [%0], [%1], 16;"
                 :: "r"(smem_dst), "l"(gmem_src) : "memory");
}

__device__ __forceinline__ void cp_commit() {
    asm volatile("cp.async.commit_group;" ::: "memory");
}

__device__ __forceinline__ void cp_wait1() {
    asm volatile("cp.async.wait_group 1;" ::: "memory");
}

__device__ __forceinline__ void ldsm4(uint32_t a[4], uint32_t addr) {
    asm volatile("ldmatrix.sync.aligned.m8n8.x4.shared.b16 {%0,%1,%2,%3}, [%4];"
        : "=r"(a[0]), "=r"(a[1]), "=r"(a[2]), "=r"(a[3]) : "r"(addr));
}

__device__ __forceinline__ uint32_t lds32(uint32_t addr) {
    uint32_t v;
    asm volatile("ld.shared.b32 %0, [%1];" : "=r"(v) : "r"(addr));
    return v;
}

__device__ __forceinline__ void mma_tf32(float c[4], const uint32_t a[4],
                                         uint32_t b0, uint32_t b1) {
    asm volatile(
        "mma.sync.aligned.m16n8k8.row.col.f32.tf32.tf32.f32 "
        "{%0,%1,%2,%3}, {%4,%5,%6,%7}, {%8,%9}, {%0,%1,%2,%3};"
        : "+f"(c[0]), "+f"(c[1]), "+f"(c[2]), "+f"(c[3])
        : "r"(a[0]), "r"(a[1]), "r"(a[2]), "r"(a[3]), "r"(b0), "r"(b1));
}

// CTA tile 128x128, 4 warps (2x2), warp tile 64x64, mma m16n8k8 tf32.
// 3-stage cp.async ring, ONE __syncthreads per iteration, fill issued before
// compute, stage-specialized steps. 2 CTAs/SM (96KB smem, <=255 regs).
// A smem: [m][32w] 128B rows, 16B-chunk swizzle ch^(m&7)  -> ldmatrix.x4 reads.
// B smem: [k][128w] 512B rows, word swizzle n^((k&7)<<3)  -> conflict-free LDS.32.
// CVT_A/CVT_B: tf32-round fragments in-loop (for raw-fp32 operands).
// FUSE: out = (acc + AddM)*scale + Mask  (QK -> g_attn); else out = acc.
template<int CVT_A, int CVT_B, int FUSE>
__global__ __launch_bounds__(THREADS, 2) void gemm_kernel(
    const float* __restrict__ Ag, const float* __restrict__ Bg,
    const float* __restrict__ AddM, const float* __restrict__ Mask,
    float* __restrict__ Out)
{
    extern __shared__ __align__(128) char smem[];
    const uint32_t sbase = smem_u32(smem);

    const int bm = blockIdx.x, bn = blockIdx.y, bh = blockIdx.z;
    const int tid  = threadIdx.x;
    const int warp = tid >> 5, lane = tid & 31;
    const int wm = warp >> 1, wn = warp & 1;   // 2 x 2 warp grid
    const int lr = lane >> 2, lc = lane & 3;

    const size_t mat = (size_t)bh * SDIM * SDIM;
    const float* Abase = Ag + mat + (size_t)(bm * 128) * SDIM;
    const float* Bbase = Bg + mat + bn * 128;

    float c[4][8][4];
    #pragma unroll
    for (int i = 0; i < 4; i++)
        #pragma unroll
        for (int j = 0; j < 8; j++)
            #pragma unroll
            for (int r = 0; r < 4; r++) c[i][j][r] = 0.f;

    // A fragment geometry (ldmatrix), verified rounds 3/5-13.
    const int moff = ((lane >> 3) & 1) * 8 + (lane & 7);
    const int csel = lane >> 4;
    uint32_t a_base[4];
    int      a_m7[4];
    #pragma unroll
    for (int ti = 0; ti < 4; ti++) {
        int m = wm * 64 + ti * 16 + moff;
        a_base[ti] = (uint32_t)m * 128u;
        a_m7[ti]   = m & 7;
    }
    // B fragment geometry: lane holds n = wn*64 + tj*8 + lr, k = kk + lc (+4).
    uint32_t nxb[8];
    #pragma unroll
    for (int tj = 0; tj < 8; tj++) {
        int n = wn * 64 + tj * 8 + lr;
        nxb[tj] = (uint32_t)((n ^ (lc << 3)) << 2);
    }

    // Per-thread fill coordinates (128 threads: 8 x 16B each for A and B).
    const int fa_r  = tid >> 3;          // A rows fa_r + 16*i
    const int fa_ch = tid & 7;
    const int fb_k  = tid >> 5;          // B k-rows fb_k + 4*i
    const int fb_nq = (tid & 31) << 2;
    uint32_t a_dst[8], b_dst[8];
    #pragma unroll
    for (int i = 0; i < 8; i++) {
        int r = fa_r + i * 16;
        a_dst[i] = (uint32_t)(r * 128 + ((fa_ch ^ (r & 7)) << 4));
        int k = fb_k + i * 4;
        b_dst[i] = (uint32_t)(16384 + k * 512 + ((fb_nq ^ ((k & 7) << 3)) << 2));
    }
    const float* aptr = Abase + (size_t)fa_r * SDIM + fa_ch * 4;
    const float* bptr = Bbase + (size_t)fb_k * SDIM + fb_nq;

    auto fill = [&](int stage, int kt) {
        const uint32_t s0 = sbase + stage * SLOT_BYTES;
        #pragma unroll
        for (int i = 0; i < 8; ++i)
            cp16(s0 + a_dst[i], aptr + kt + (size_t)i * 16 * SDIM);
        #pragma unroll
        for (int i = 0; i < 8; ++i)
            cp16(s0 + b_dst[i], bptr + (size_t)(kt + i * 4) * SDIM);
    };

    auto compute = [&](int stage) {
        const uint32_t sA = sbase + stage * SLOT_BYTES;
        const uint32_t sB = sA + 16384;
        #pragma unroll
        for (int kk4 = 0; kk4 < 4; ++kk4) {
            uint32_t af[4][4];
            const int chunk = (kk4 << 1) + csel;
            #pragma unroll
            for (int ti = 0; ti < 4; ++ti)
                ldsm4(af[ti], sA + a_base[ti] + (uint32_t)((chunk ^ a_m7[ti]) << 4));

            uint32_t b0[8], b1[8];
            const uint32_t row0 = sB + (uint32_t)((kk4 << 3) + lc) * 512u;
            const uint32_t row1 = row0 + 2048u;
            #pragma unroll
            for (int tj = 0; tj < 8; ++tj) {
                b0[tj] = lds32(row0 + nxb[tj]);
                b1[tj] = lds32(row1 + (nxb[tj] ^ 128u));
            }
            if (CVT_A) {
                #pragma unroll
                for (int ti = 0; ti < 4; ++ti)
                    #pragma unroll
                    for (int j = 0; j < 4; ++j)
                        af[ti][j] = f2tf(__uint_as_float(af[ti][j]));
            }
            if (CVT_B) {
                #pragma unroll
                for (int tj = 0; tj < 8; ++tj) {
                    b0[tj] = f2tf(__uint_as_float(b0[tj]));
                    b1[tj] = f2tf(__uint_as_float(b1[tj]));
                }
            }
            #pragma unroll
            for (int ti = 0; ti < 4; ++ti)
                #pragma unroll
                for (int tj = 0; tj < 8; ++tj)
                    mma_tf32(c[ti][tj], af[ti], b0[tj], b1[tj]);
        }
    };

    // One pipeline step: wait tile `it`, publish, issue fill for tile it+2
    // (slot last read at it-1 -> WAR fenced by the barrier), compute tile `it`.
    auto step = [&](int it, int stage) {
        cp_wait1();
        __syncthreads();
        if (it + 2 < 32) { fill((it + 2) % STAGES, (it + 2) << 5); }
        cp_commit();
        compute(stage);
    };

    // Prologue: STAGES-1 tiles in flight.
    fill(0, 0);  cp_commit();
    fill(1, 32); cp_commit();

    #pragma unroll 1
    for (int it = 0; it < 30; it += 3) {
        step(it + 0, 0);
        step(it + 1, 1);
        step(it + 2, 2);
    }
    step(30, 0);
    step(31, 1);

    // ---- epilogue ----
    const float scale = 0.03125f;  // 1/sqrt(1024)
    #pragma unroll
    for (int ti = 0; ti < 4; ti++) {
        #pragma unroll
        for (int tj = 0; tj < 8; tj++) {
            int i0 = bm * 128 + wm * 64 + ti * 16 + lr;
            int j0 = bn * 128 + wn * 64 + tj * 8 + lc * 2;
            #pragma unroll
            for (int h = 0; h < 2; h++) {
                int i = i0 + h * 8;
                float v0 = c[ti][tj][h * 2 + 0];
                float v1 = c[ti][tj][h * 2 + 1];
                size_t off = mat + (size_t)i * SDIM + j0;
                if (FUSE) {
                    float2 bb = *reinterpret_cast<const float2*>(AddM + off);
                    float2 mm = *reinterpret_cast<const float2*>(
                        Mask + (size_t)i * SDIM + j0);
                    v0 = (v0 + bb.x) * scale + mm.x;
                    v1 = (v1 + bb.y) * scale + mm.y;
                }
                float2 o; o.x = v0; o.y = v1;
                *reinterpret_cast<float2*>(Out + off) = o;
            }
        }
    }
}

// One CTA (256 threads) per row; in-place softmax, tf32-rounded output.
__global__ __launch_bounds__(256) void softmax_kernel() {
    const size_t row = blockIdx.x;
    float* p = g_attn + row * SDIM;
    const int tid = threadIdx.x;
    const int warp = tid >> 5, lane = tid & 31;
    __shared__ float sred[8];

    float4 v = reinterpret_cast<float4*>(p)[tid];

    float m = fmaxf(fmaxf(v.x, v.y), fmaxf(v.z, v.w));
    #pragma unroll
    for (int o = 16; o; o >>= 1) m = fmaxf(m, __shfl_xor_sync(0xffffffffu, m, o));
    if (lane == 0) sred[warp] = m;
    __syncthreads();
    m = sred[0];
    #pragma unroll
    for (int i = 1; i < 8; i++) m = fmaxf(m, sred[i]);
    __syncthreads();

    v.x = __expf(v.x - m);
    v.y = __expf(v.y - m);
    v.z = __expf(v.z - m);
    v.w = __expf(v.w - m);
    float s = v.x + v.y + v.z + v.w;
    #pragma unroll
    for (int o = 16; o; o >>= 1) s += __shfl_xor_sync(0xffffffffu, s, o);
    if (lane == 0) sred[warp] = s;
    __syncthreads();
    s = sred[0];
    #pragma unroll
    for (int i = 1; i < 8; i++) s += sred[i];

    float inv = 1.0f / s;
    v.x = __uint_as_float(f2tf(v.x * inv));
    v.y = __uint_as_float(f2tf(v.y * inv));
    v.z = __uint_as_float(f2tf(v.z * inv));
    v.w = __uint_as_float(f2tf(v.w * inv));
    reinterpret_cast<float4*>(p)[tid] = v;
}

extern "C" void kernel_launch(void* const* d_in, const int* in_sizes, int n_in,
                              void* d_out, int out_size) {
    const float* A    = (const float*)d_in[0];
    const float* J    = (const float*)d_in[1];
    const float* B    = (const float*)d_in[2];
    const float* P    = (const float*)d_in[3];
    const float* mask = (const float*)d_in[4];
    float* out = (float*)d_out;

    float* attn = nullptr;
    cudaGetSymbolAddress((void**)&attn, g_attn);

    cudaFuncSetAttribute(gemm_kernel<1, 1, 1>,
                         cudaFuncAttributeMaxDynamicSharedMemorySize, SMEM_BYTES);
    cudaFuncSetAttribute(gemm_kernel<0, 1, 0>,
                         cudaFuncAttributeMaxDynamicSharedMemorySize, SMEM_BYTES);

    dim3 grid(SDIM / 128, SDIM / 128, BHN);  // 8 x 8 x 64

    // gemm1: raw A x raw J (cvt both in-loop), fused (+B)*scale+mask epilogue.
    gemm_kernel<1, 1, 1><<<grid, THREADS, SMEM_BYTES>>>(A, J, B, mask, attn);
    // softmax emits tf32-rounded probs -> gemm2 converts only P in-loop.
    softmax_kernel<<<BHN * SDIM, 256>>>();
    gemm_kernel<0, 1, 0><<<grid, THREADS, SMEM_BYTES>>>(attn, P, nullptr, nullptr, out);
}